// round 11
// baseline (speedup 1.0000x reference)
#include <cuda_runtime.h>
#include <cuda_bf16.h>

// Blockwise 256-point regular Hadamard transform (H = kron(H4 x4) / 16).
// Fast transform, 4 radix-4 stages on independent base-4 digits (stages
// commute -> ONE smem transpose per tile; 80 L1-wavefronts/warp-tile is
// the proven structural floor).
//
// R9: 2-tile pipeline with DOUBLE-BUFFERED smem and a single merged
// __syncwarp. Schedule per warp:
//   [8x LDG.128 (A+B)] [stages01 A] [STS A->bufA] [stages01 B] [STS B->bufB]
//   __syncwarp
//   [LDS A] [stages23 A] [STG A] [LDS B] [stages23 B] [STG B]
// Loads are maximally front-loaded (MLP=8), syncs 3 -> 1, tile A's store
// drain overlaps tile B's butterflies.

#define BF4(a,b,c,d)                                   \
    do {                                               \
        float _s = ((a)+(b)) + ((c)+(d));              \
        float _ta=(a), _tb=(b), _tc=(c);               \
        (a) = fmaf(-2.0f, (d), _s);                    \
        (b) = fmaf(-2.0f, _tc, _s);                    \
        (c) = fmaf(-2.0f, _tb, _s);                    \
        (d) = fmaf(-2.0f, _ta, _s);                    \
    } while (0)

// Last stage with folded 1/16 scale: y/16 = fma(-2/16, x, s/16).
#define BF4S(a,b,c,d)                                  \
    do {                                               \
        float _s = (((a)+(b)) + ((c)+(d))) * 0.0625f;  \
        float _ta=(a), _tb=(b), _tc=(c);               \
        (a) = fmaf(-0.125f, (d), _s);                  \
        (b) = fmaf(-0.125f, _tc, _s);                  \
        (c) = fmaf(-0.125f, _tb, _s);                  \
        (d) = fmaf(-0.125f, _ta, _s);                  \
    } while (0)

#define RS 20    // smem row stride in floats (80B, 16B-aligned)
#define SB 336   // smem block stride in floats (336 mod 32 == 16)

#define LOAD16(dst, ptr)                                                   \
    do {                                                                   \
        float4 _p;                                                         \
        _p = __ldcs((ptr) + 0); dst[0]=_p.x;  dst[1]=_p.y;  dst[2]=_p.z;  dst[3]=_p.w;  \
        _p = __ldcs((ptr) + 1); dst[4]=_p.x;  dst[5]=_p.y;  dst[6]=_p.z;  dst[7]=_p.w;  \
        _p = __ldcs((ptr) + 2); dst[8]=_p.x;  dst[9]=_p.y;  dst[10]=_p.z; dst[11]=_p.w; \
        _p = __ldcs((ptr) + 3); dst[12]=_p.x; dst[13]=_p.y; dst[14]=_p.z; dst[15]=_p.w; \
    } while (0)

#define STAGES01(v)                    \
    do {                               \
        BF4(v[0], v[1], v[2],  v[3]);  \
        BF4(v[4], v[5], v[6],  v[7]);  \
        BF4(v[8], v[9], v[10], v[11]); \
        BF4(v[12],v[13],v[14], v[15]); \
        BF4(v[0], v[4], v[8],  v[12]); \
        BF4(v[1], v[5], v[9],  v[13]); \
        BF4(v[2], v[6], v[10], v[14]); \
        BF4(v[3], v[7], v[11], v[15]); \
    } while (0)

#define STAGES23S(w)                    \
    do {                                \
        BF4(w[0], w[1], w[2],  w[3]);   \
        BF4(w[4], w[5], w[6],  w[7]);   \
        BF4(w[8], w[9], w[10], w[11]);  \
        BF4(w[12],w[13],w[14], w[15]);  \
        BF4S(w[0], w[4], w[8],  w[12]); \
        BF4S(w[1], w[5], w[9],  w[13]); \
        BF4S(w[2], w[6], w[10], w[14]); \
        BF4S(w[3], w[7], w[11], w[15]); \
    } while (0)

#define LDROW(w, base)                                                     \
    do {                                                                   \
        const float4* _rp = reinterpret_cast<const float4*>(base);         \
        float4 _a;                                                         \
        _a = _rp[0]; w[0]=_a.x;  w[1]=_a.y;  w[2]=_a.z;  w[3]=_a.w;        \
        _a = _rp[1]; w[4]=_a.x;  w[5]=_a.y;  w[6]=_a.z;  w[7]=_a.w;        \
        _a = _rp[2]; w[8]=_a.x;  w[9]=_a.y;  w[10]=_a.z; w[11]=_a.w;       \
        _a = _rp[3]; w[12]=_a.x; w[13]=_a.y; w[14]=_a.z; w[15]=_a.w;       \
    } while (0)

#define STORE16(w, yo)                                                     \
    do {                                                                   \
        _Pragma("unroll")                                                  \
        for (int _k = 0; _k < 16; _k++)                                    \
            __stcs((yo) + (_k << 4), w[_k]);                               \
    } while (0)

__global__ __launch_bounds__(256, 5) void had256_kernel(
    const float* __restrict__ x, float* __restrict__ y)
{
    __shared__ __align__(16) float smA[16 * SB];
    __shared__ __align__(16) float smB[16 * SB];

    const int tid = threadIdx.x;
    const int h   = tid >> 4;        // hadamard block within tile [0,16)
    const int j   = tid & 15;        // lane within 16-group [0,16)
    const int sbase = h * SB;

    // CTA covers 8192 consecutive floats = two 4KB tiles.
    const size_t blkA = ((size_t)blockIdx.x << 13) + ((size_t)h << 8);
    const size_t blkB = blkA + 4096;

    // ---- issue ALL global loads up front (8 LDG.128 in flight) ----
    const float4* xa = reinterpret_cast<const float4*>(x + blkA + ((size_t)j << 4));
    const float4* xb = reinterpret_cast<const float4*>(x + blkB + ((size_t)j << 4));
    float va[16], vb[16];
    LOAD16(va, xa);
    LOAD16(vb, xb);

    // ---- front half: stages 0-1 + transpose writes, both tiles ----
    STAGES01(va);
    #pragma unroll
    for (int i = 0; i < 16; i++)
        smA[sbase + i * RS + j] = va[i];     // va dead

    STAGES01(vb);
    #pragma unroll
    for (int i = 0; i < 16; i++)
        smB[sbase + i * RS + j] = vb[i];     // vb dead

    __syncwarp();                            // single sync for both tiles

    // ---- back half: read rows, stages 2-3, store; tile A then B ----
    float w[16];

    LDROW(w, smA + sbase + j * RS);
    STAGES23S(w);
    STORE16(w, y + blkA + j);

    LDROW(w, smB + sbase + j * RS);
    STAGES23S(w);
    STORE16(w, y + blkB + j);
}

extern "C" void kernel_launch(void* const* d_in, const int* in_sizes, int n_in,
                              void* d_out, int out_size)
{
    // x = largest input; H is the fixed regular Hadamard matrix, applied
    // analytically by the fast transform (never read).
    int xi = 0;
    long long best = -1;
    for (int i = 0; i < n_in; i++) {
        if ((long long)in_sizes[i] > best) { best = in_sizes[i]; xi = i; }
    }
    const float* x = (const float*)d_in[xi];
    float*       y = (float*)d_out;

    // 8192 elements (two 16-block tiles) per CTA.
    int nblocks = out_size >> 13;   // 67108864 -> 8192 CTAs
    had256_kernel<<<nblocks, 256>>>(x, y);
}

// round 13
// speedup vs baseline: 1.0541x; 1.0541x over previous
#include <cuda_runtime.h>
#include <cuda_bf16.h>

// Blockwise 256-point regular Hadamard transform (H = kron(H4 x4) / 16).
// Fast transform, 4 radix-4 stages on independent base-4 digits (stages
// commute -> ONE smem transpose; 80 L1-wavefronts/warp-tile structural floor).
//
// R11: persistent grid-stride CTAs (912 CTAs, ~18 tiles each) with in-loop
// prefetch. Per iteration:
//   [stages01 v] [syncwarp] [STS v]  <-- v dead here
//   [LOAD16 v <- NEXT tile]          <-- 4 LDG.128 overlap the whole back half
//   [syncwarp] [LDS w] [stages23 w] [STG w]
// Registers capped by __launch_bounds__(256,6) (<=42, no spills) -> 48
// warps/SM; removes per-tile exposed load latency and CTA launch waves.

#define BF4(a,b,c,d)                                   \
    do {                                               \
        float _s = ((a)+(b)) + ((c)+(d));              \
        float _ta=(a), _tb=(b), _tc=(c);               \
        (a) = fmaf(-2.0f, (d), _s);                    \
        (b) = fmaf(-2.0f, _tc, _s);                    \
        (c) = fmaf(-2.0f, _tb, _s);                    \
        (d) = fmaf(-2.0f, _ta, _s);                    \
    } while (0)

// Last stage with folded 1/16 scale: y/16 = fma(-2/16, x, s/16).
#define BF4S(a,b,c,d)                                  \
    do {                                               \
        float _s = (((a)+(b)) + ((c)+(d))) * 0.0625f;  \
        float _ta=(a), _tb=(b), _tc=(c);               \
        (a) = fmaf(-0.125f, (d), _s);                  \
        (b) = fmaf(-0.125f, _tc, _s);                  \
        (c) = fmaf(-0.125f, _tb, _s);                  \
        (d) = fmaf(-0.125f, _ta, _s);                  \
    } while (0)

#define RS 20    // smem row stride in floats (80B, 16B-aligned)
#define SB 336   // smem block stride in floats (336 mod 32 == 16)

#define LOAD16(dst, ptr)                                                   \
    do {                                                                   \
        float4 _p;                                                         \
        _p = __ldcs((ptr) + 0); dst[0]=_p.x;  dst[1]=_p.y;  dst[2]=_p.z;  dst[3]=_p.w;  \
        _p = __ldcs((ptr) + 1); dst[4]=_p.x;  dst[5]=_p.y;  dst[6]=_p.z;  dst[7]=_p.w;  \
        _p = __ldcs((ptr) + 2); dst[8]=_p.x;  dst[9]=_p.y;  dst[10]=_p.z; dst[11]=_p.w; \
        _p = __ldcs((ptr) + 3); dst[12]=_p.x; dst[13]=_p.y; dst[14]=_p.z; dst[15]=_p.w; \
    } while (0)

#define STAGES01(v)                    \
    do {                               \
        BF4(v[0], v[1], v[2],  v[3]);  \
        BF4(v[4], v[5], v[6],  v[7]);  \
        BF4(v[8], v[9], v[10], v[11]); \
        BF4(v[12],v[13],v[14], v[15]); \
        BF4(v[0], v[4], v[8],  v[12]); \
        BF4(v[1], v[5], v[9],  v[13]); \
        BF4(v[2], v[6], v[10], v[14]); \
        BF4(v[3], v[7], v[11], v[15]); \
    } while (0)

#define STAGES23S(w)                    \
    do {                                \
        BF4(w[0], w[1], w[2],  w[3]);   \
        BF4(w[4], w[5], w[6],  w[7]);   \
        BF4(w[8], w[9], w[10], w[11]);  \
        BF4(w[12],w[13],w[14], w[15]);  \
        BF4S(w[0], w[4], w[8],  w[12]); \
        BF4S(w[1], w[5], w[9],  w[13]); \
        BF4S(w[2], w[6], w[10], w[14]); \
        BF4S(w[3], w[7], w[11], w[15]); \
    } while (0)

#define LDROW(w, base)                                                     \
    do {                                                                   \
        const float4* _rp = reinterpret_cast<const float4*>(base);         \
        float4 _a;                                                         \
        _a = _rp[0]; w[0]=_a.x;  w[1]=_a.y;  w[2]=_a.z;  w[3]=_a.w;        \
        _a = _rp[1]; w[4]=_a.x;  w[5]=_a.y;  w[6]=_a.z;  w[7]=_a.w;        \
        _a = _rp[2]; w[8]=_a.x;  w[9]=_a.y;  w[10]=_a.z; w[11]=_a.w;       \
        _a = _rp[3]; w[12]=_a.x; w[13]=_a.y; w[14]=_a.z; w[15]=_a.w;       \
    } while (0)

__global__ __launch_bounds__(256, 6) void had256_kernel(
    const float* __restrict__ x, float* __restrict__ y, int ntiles)
{
    __shared__ __align__(16) float sm[16 * SB];

    const int tid = threadIdx.x;
    const int h   = tid >> 4;        // hadamard block within tile [0,16)
    const int j   = tid & 15;        // lane within 16-group [0,16)
    const int sbase = h * SB;
    const int stride = gridDim.x;    // persistent grid stride (tiles)

    // per-thread offset inside a tile (elements)
    const size_t toff_ld = ((size_t)h << 8) + ((size_t)j << 4);  // load base
    const size_t toff_st = ((size_t)h << 8) + (size_t)j;         // store base

    int t = blockIdx.x;

    float v[16], w[16];
    LOAD16(v, reinterpret_cast<const float4*>(x + ((size_t)t << 12) + toff_ld));

    for (;;) {
        const bool last = (t + stride >= ntiles);
        const int  tn   = last ? t : t + stride;   // clamp: harmless re-read

        // ---- front half: stages 0-1, transpose write ----
        STAGES01(v);

        __syncwarp();    // all lanes done reading previous iteration's rows
        #pragma unroll
        for (int i = 0; i < 16; i++)
            sm[sbase + i * RS + j] = v[i];         // v dead

        // ---- prefetch next tile into v (overlaps entire back half) ----
        LOAD16(v, reinterpret_cast<const float4*>(x + ((size_t)tn << 12) + toff_ld));

        __syncwarp();

        // ---- back half: read rows, stages 2-3, store ----
        LDROW(w, sm + sbase + j * RS);
        STAGES23S(w);

        {
            float* yo = y + ((size_t)t << 12) + toff_st;
            #pragma unroll
            for (int k = 0; k < 16; k++)
                __stcs(yo + (k << 4), w[k]);
        }

        if (last) break;
        t = tn;
    }
}

extern "C" void kernel_launch(void* const* d_in, const int* in_sizes, int n_in,
                              void* d_out, int out_size)
{
    // x = largest input; H is the fixed regular Hadamard matrix, applied
    // analytically by the fast transform (never read).
    int xi = 0;
    long long best = -1;
    for (int i = 0; i < n_in; i++) {
        if ((long long)in_sizes[i] > best) { best = in_sizes[i]; xi = i; }
    }
    const float* x = (const float*)d_in[xi];
    float*       y = (float*)d_out;

    int ntiles = out_size >> 12;             // 4KB tiles (16384)
    int grid   = 912;                        // ~6 CTA/SM x 152 SMs, persistent
    if (grid > ntiles) grid = ntiles;
    had256_kernel<<<grid, 256>>>(x, y, ntiles);
}

// round 14
// speedup vs baseline: 1.2244x; 1.1616x over previous
#include <cuda_runtime.h>
#include <cuda_bf16.h>

// Blockwise 256-point regular Hadamard transform (H = kron(H4 x4) / 16).
// Fast transform, 4 radix-4 stages on independent base-4 digits (stages
// commute -> ONE smem transpose). Proven R5 dataflow (82.0us):
//   1. 4x LDG.128: thread (h,j) holds elements e = 16j+i of block h
//   2. butterfly d0,d1 in registers (strides 1,4)
//   3. smem transpose: 16 scalar STS (CF) + 4 LDS.128 (CF), RS=20/SB=336
//   4. thread holds e = 16k+j; butterfly d2,d3 (element strides 16,64 =
//      register strides 1,4); 1/16 scale folded into last stage
//   5. 16 scalar STG.32 (dense 64B segment per 16-lane group)
//
// R13: 128-thread CTAs (4 warps, 8 blocks/CTA, grid 32768). Same warp-
// internal layout (bank-conflict proofs unchanged), same 32-reg envelope;
// 16 CTAs/SM (RF-bound: 32*128*16 = 65536) = 64 warps. Finer CTA
// granularity smooths launch/drain residency + wave tails that capped
// measured occupancy at 84.7% with 256-thread CTAs.
// (80 L1-wavefronts/warp is the verified structural floor; R8/R9/R11
// showed regs>32 or warps<64/SM always lose.)

#define BF4(a,b,c,d)                                   \
    do {                                               \
        float _s = ((a)+(b)) + ((c)+(d));              \
        float _ta=(a), _tb=(b), _tc=(c);               \
        (a) = fmaf(-2.0f, (d), _s);                    \
        (b) = fmaf(-2.0f, _tc, _s);                    \
        (c) = fmaf(-2.0f, _tb, _s);                    \
        (d) = fmaf(-2.0f, _ta, _s);                    \
    } while (0)

// Last stage with folded 1/16 scale: y/16 = fma(-2/16, x, s/16).
#define BF4S(a,b,c,d)                                  \
    do {                                               \
        float _s = (((a)+(b)) + ((c)+(d))) * 0.0625f;  \
        float _ta=(a), _tb=(b), _tc=(c);               \
        (a) = fmaf(-0.125f, (d), _s);                  \
        (b) = fmaf(-0.125f, _tc, _s);                  \
        (c) = fmaf(-0.125f, _tb, _s);                  \
        (d) = fmaf(-0.125f, _ta, _s);                  \
    } while (0)

#define RS 20    // smem row stride in floats (80B, 16B-aligned)
#define SB 336   // smem block stride in floats (336 mod 32 == 16)
#define NB 8     // hadamard blocks per CTA (128 threads)

__global__ __launch_bounds__(128) void had256_kernel(
    const float* __restrict__ x, float* __restrict__ y)
{
    __shared__ __align__(16) float sm[NB * SB];

    const unsigned tid = threadIdx.x;
    const unsigned h   = tid >> 4;          // block within CTA [0,8)
    const unsigned j   = tid & 15;          // lane within 16-group [0,16)
    const unsigned sbase = h * SB;

    // CTA covers 2048 consecutive floats = 8 blocks of 256.
    const size_t blk = ((size_t)blockIdx.x << 11) + ((size_t)(h << 8));

    // ---- load 16 consecutive floats: e = 16j + i ----
    const float4* xin = reinterpret_cast<const float4*>(x + blk + (j << 4));
    float v[16];
    {
        float4 p;
        p = __ldcs(xin + 0); v[0]=p.x;  v[1]=p.y;  v[2]=p.z;  v[3]=p.w;
        p = __ldcs(xin + 1); v[4]=p.x;  v[5]=p.y;  v[6]=p.z;  v[7]=p.w;
        p = __ldcs(xin + 2); v[8]=p.x;  v[9]=p.y;  v[10]=p.z; v[11]=p.w;
        p = __ldcs(xin + 3); v[12]=p.x; v[13]=p.y; v[14]=p.z; v[15]=p.w;
    }

    // ---- stage d0 (element stride 1 = reg stride 1) ----
    BF4(v[0], v[1], v[2],  v[3]);
    BF4(v[4], v[5], v[6],  v[7]);
    BF4(v[8], v[9], v[10], v[11]);
    BF4(v[12],v[13],v[14], v[15]);
    // ---- stage d1 (element stride 4 = reg stride 4) ----
    BF4(v[0], v[4], v[8],  v[12]);
    BF4(v[1], v[5], v[9],  v[13]);
    BF4(v[2], v[6], v[10], v[14]);
    BF4(v[3], v[7], v[11], v[15]);

    // ---- single transpose: element 16j+i -> row i, col j (scalar STS, CF) ----
    #pragma unroll
    for (int i = 0; i < 16; i++)
        sm[sbase + i * RS + j] = v[i];

    __syncwarp();

    // vector LDS: thread j reads row j -> w[k] = element 16k + j (CF).
    float w[16];
    {
        const float4* rp = reinterpret_cast<const float4*>(sm + sbase + j * RS);
        float4 a;
        a = rp[0]; w[0]=a.x;  w[1]=a.y;  w[2]=a.z;  w[3]=a.w;
        a = rp[1]; w[4]=a.x;  w[5]=a.y;  w[6]=a.z;  w[7]=a.w;
        a = rp[2]; w[8]=a.x;  w[9]=a.y;  w[10]=a.z; w[11]=a.w;
        a = rp[3]; w[12]=a.x; w[13]=a.y; w[14]=a.z; w[15]=a.w;
    }

    // ---- stage d2 (element stride 16 = reg stride 1) ----
    BF4(w[0], w[1], w[2],  w[3]);
    BF4(w[4], w[5], w[6],  w[7]);
    BF4(w[8], w[9], w[10], w[11]);
    BF4(w[12],w[13],w[14], w[15]);
    // ---- stage d3 (element stride 64 = reg stride 4) + 1/16 scale ----
    BF4S(w[0], w[4], w[8],  w[12]);
    BF4S(w[1], w[5], w[9],  w[13]);
    BF4S(w[2], w[6], w[10], w[14]);
    BF4S(w[3], w[7], w[11], w[15]);

    // ---- scalar store: w[k] -> y[blk + 16k + j] ----
    // Per instr (fixed k) each 16-lane group writes one dense 64B segment.
    float* yo = y + blk + j;
    #pragma unroll
    for (int k = 0; k < 16; k++)
        __stcs(yo + (k << 4), w[k]);
}

extern "C" void kernel_launch(void* const* d_in, const int* in_sizes, int n_in,
                              void* d_out, int out_size)
{
    // x = largest input; H is the fixed regular Hadamard matrix, applied
    // analytically by the fast transform (never read).
    int xi = 0;
    long long best = -1;
    for (int i = 0; i < n_in; i++) {
        if ((long long)in_sizes[i] > best) { best = in_sizes[i]; xi = i; }
    }
    const float* x = (const float*)d_in[xi];
    float*       y = (float*)d_out;

    // 2048 elements (8 Hadamard blocks) per 128-thread CTA.
    int nblocks = out_size >> 11;   // 67108864 -> 32768 CTAs
    had256_kernel<<<nblocks, 128>>>(x, y);
}